// round 7
// baseline (speedup 1.0000x reference)
#include <cuda_runtime.h>
#include <math.h>

#define N_NODES    100000
#define N_EDGES    1600000
#define NUM_GRAPHS 4096
#define HID        128
#define F_IN       11
#define F_OUT      19
#define P1         16      // padded input row (floats)
#define P2         24      // padded z row (floats)
#define WCP        20      // padded Wc columns (col 19 = zero)
#define SCAN_B     512
#define SCAN_NB    ((N_NODES + SCAN_B - 1) / SCAN_B)
#define NB_HIST    ((N_EDGES + 255) / 256)
// tail work in k_hist: pool zero | cnt zero | Wc | bc
#define TAIL_POOL  (NUM_GRAPHS * F_OUT)
#define TAIL_CNT   (TAIL_POOL + NUM_GRAPHS)
#define TAIL_WC    (TAIL_CNT + HID * WCP)
#define TAIL_BC    (TAIL_WC + F_OUT)
#define NB_TAIL    ((TAIL_BC + 255) / 256)

#define G2_TILE    128
#define G2_HSTRIDE 132
#define XA_STRIDE  17

// ---------------- static device scratch (zero-initialized at load) ----------------
__device__ float g_xs [(size_t)N_NODES * P1];   // dinv-scaled padded input
__device__ float g_z  [(size_t)N_NODES * P2];   // dinv * (h1 @ Wc)
__device__ float g_Wc [HID * WCP];              // W2 @ Wlin (padded)
__device__ float g_bc [F_OUT];                  // b2 @ Wlin + blin
__device__ float g_dinv[N_NODES];
__device__ int   g_ecnt[N_NODES];               // self-cleaned by k_scan23
__device__ int   g_rank[N_EDGES];               // rank of edge within its dst bucket
__device__ int   g_rowptr[N_NODES + 1];
__device__ int   g_csr[N_EDGES];
__device__ int   g_blksum[SCAN_NB];
__device__ float g_pool[NUM_GRAPHS * F_OUT];    // zeroed in k_hist tail
__device__ int   g_cnt[NUM_GRAPHS];             // zeroed in k_hist tail

// ---------------- hist over dst (stores rank) + tail: zero pool/cnt, Wc, bc ----------------
__global__ void k_hist(const int* __restrict__ dst,
                       const float* __restrict__ W2, const float* __restrict__ Wlin,
                       const float* __restrict__ b2, const float* __restrict__ blin) {
    int b = blockIdx.x;
    if (b < NB_HIST) {
        int e = b * 256 + threadIdx.x;
        if (e < N_EDGES) {
            int d = __ldg(&dst[e]);
            g_rank[e] = atomicAdd(&g_ecnt[d], 1);
        }
        return;
    }
    int j = (b - NB_HIST) * 256 + threadIdx.x;
    if (j < TAIL_POOL) { g_pool[j] = 0.0f; return; }
    if (j < TAIL_CNT)  { g_cnt[j - TAIL_POOL] = 0; return; }
    if (j < TAIL_WC) {
        int i = j - TAIL_CNT;
        int k = i / WCP, f = i % WCP;
        float acc = 0.0f;
        if (f < F_OUT) {
            #pragma unroll 8
            for (int m = 0; m < HID; m++)
                acc += __ldg(&W2[k * HID + m]) * __ldg(&Wlin[m * F_OUT + f]);
        }
        g_Wc[i] = acc;
        return;
    }
    if (j < TAIL_BC) {
        int f = j - TAIL_WC;
        float acc = __ldg(&blin[f]);
        #pragma unroll 8
        for (int m = 0; m < HID; m++)
            acc += __ldg(&b2[m]) * __ldg(&Wlin[m * F_OUT + f]);
        g_bc[f] = acc;
    }
}

// ---------------- scan phase 1: per-block exclusive scan of g_ecnt ----------------
__global__ void k_scan1() {
    __shared__ int warp_sums[16];
    int i = blockIdx.x * SCAN_B + threadIdx.x;
    int v = (i < N_NODES) ? g_ecnt[i] : 0;
    int lane = threadIdx.x & 31, wid = threadIdx.x >> 5;
    int incl = v;
    #pragma unroll
    for (int d = 1; d < 32; d <<= 1) {
        int t = __shfl_up_sync(0xffffffffu, incl, d);
        if (lane >= d) incl += t;
    }
    if (lane == 31) warp_sums[wid] = incl;
    __syncthreads();
    if (wid == 0) {
        int s = (lane < 16) ? warp_sums[lane] : 0;
        #pragma unroll
        for (int d = 1; d < 16; d <<= 1) {
            int t = __shfl_up_sync(0xffffffffu, s, d);
            if (lane >= d) s += t;
        }
        if (lane < 16) warp_sums[lane] = s;
    }
    __syncthreads();
    int offset = (wid > 0) ? warp_sums[wid - 1] : 0;
    if (i < N_NODES) g_rowptr[i] = offset + incl - v;
    if (threadIdx.x == SCAN_B - 1) g_blksum[blockIdx.x] = offset + incl;
}

// ---------------- scan 2+3 fused: every block scans blksum in smem, then finalizes ----------------
// also: dinv, xs = dinv*x (padded), ecnt self-clean, rowptr tail
__global__ void k_scan23(const float* __restrict__ x) {
    __shared__ int pref[SCAN_NB];
    __shared__ int ws[8];
    int tid = threadIdx.x;                      // 256
    {
        int lane = tid & 31, w = tid >> 5;
        int v = (tid < SCAN_NB) ? g_blksum[tid] : 0;
        int incl = v;
        #pragma unroll
        for (int d = 1; d < 32; d <<= 1) {
            int u = __shfl_up_sync(0xffffffffu, incl, d);
            if (lane >= d) incl += u;
        }
        if (lane == 31) ws[w] = incl;
        __syncthreads();
        if (w == 0) {
            int s = (lane < 8) ? ws[lane] : 0;
            #pragma unroll
            for (int d = 1; d < 8; d <<= 1) {
                int u = __shfl_up_sync(0xffffffffu, s, d);
                if (lane >= d) s += u;
            }
            if (lane < 8) ws[lane] = s;
        }
        __syncthreads();
        int off = (w > 0) ? ws[w - 1] : 0;
        if (tid < SCAN_NB) pref[tid] = off + incl - v;
        __syncthreads();
    }
    int i = blockIdx.x * 256 + tid;
    if (i >= N_NODES) return;
    if (i == 0) g_rowptr[N_NODES] = N_EDGES;
    int r = g_rowptr[i] + pref[i / SCAN_B];
    g_rowptr[i] = r;
    int e = g_ecnt[i];
    g_ecnt[i] = 0;                               // self-clean for next replay
    float d = rsqrtf((float)(e + 1));
    g_dinv[i] = d;
    float row[P1];
    #pragma unroll
    for (int f = 0; f < F_IN; f++) row[f] = __ldg(&x[i * F_IN + f]) * d;
    #pragma unroll
    for (int f = F_IN; f < P1; f++) row[f] = 0.0f;
    float4* dst = (float4*)(g_xs + (size_t)i * P1);
    dst[0] = make_float4(row[0], row[1], row[2], row[3]);
    dst[1] = make_float4(row[4], row[5], row[6], row[7]);
    dst[2] = make_float4(row[8], row[9], row[10], row[11]);
    dst[3] = make_float4(row[12], row[13], row[14], row[15]);
}

// ---------------- CSR fill: atomic-free (rank precomputed in hist) ----------------
__global__ void k_fill(const int* __restrict__ src, const int* __restrict__ dst) {
    int e = blockIdx.x * blockDim.x + threadIdx.x;
    if (e < N_EDGES) {
        int d = __ldg(&dst[e]);
        int p = __ldg(&g_rowptr[d]) + g_rank[e];
        g_csr[p] = __ldg(&src[e]);
    }
}

// ---------------- fused agg1 + GEMM1 + GEMM2': block owns 128-node tile ----------------
// stage 1: 16 half-warps gather xa for 8 nodes each -> sXA (stride 17)
// stage 2 (phase A): h1 = relu(dinv*xa @ W1 + b1) -> sH (stride 132)
// stage 3 (phase B): z = dinv * (h1 @ Wc) -> g_z
__global__ void k_agg1gemm(const float* __restrict__ W1, const float* __restrict__ b1) {
    extern __shared__ float sh[];
    float* sH  = sh;                            // [128][132]
    float* sWc = sh + G2_TILE * G2_HSTRIDE;     // [128][20]
    float* sXA = sWc + HID * WCP;               // [128][17]
    int tid = threadIdx.x;                      // 256
    int lane = tid & 31, w = tid >> 5;          // 8 warps
    int base = blockIdx.x * G2_TILE;

    for (int i = tid; i < HID * WCP; i += 256) sWc[i] = g_Wc[i];

    // stage 1: aggregation into sXA
    int hw = tid >> 4, hl = tid & 15;           // 16 half-warps
    for (int r = 0; r < 8; r++) {
        int nl = hw * 8 + r;
        int node = base + nl;
        float acc = 0.0f;
        if (node < N_NODES) {
            acc = g_xs[(size_t)node * P1 + hl];  // self loop
            int j = g_rowptr[node], end = g_rowptr[node + 1];
            for (; j + 4 <= end; j += 4) {
                int s0 = __ldg(&g_csr[j]);
                int s1 = __ldg(&g_csr[j + 1]);
                int s2 = __ldg(&g_csr[j + 2]);
                int s3 = __ldg(&g_csr[j + 3]);
                acc += g_xs[(size_t)s0 * P1 + hl] + g_xs[(size_t)s1 * P1 + hl]
                     + g_xs[(size_t)s2 * P1 + hl] + g_xs[(size_t)s3 * P1 + hl];
            }
            for (; j < end; j++)
                acc += g_xs[(size_t)__ldg(&g_csr[j]) * P1 + hl];
        }
        sXA[nl * XA_STRIDE + hl] = acc;
    }
    __syncthreads();

    // stage 2 (phase A): warp w computes nodes [w*16, w*16+16) -> sH
    float4 w1r[F_IN];
    #pragma unroll
    for (int k = 0; k < F_IN; k++)
        w1r[k] = __ldg(((const float4*)(W1 + k * HID)) + lane);
    float4 bb = __ldg(((const float4*)b1) + lane);

    #pragma unroll 2
    for (int rep = 0; rep < 16; rep++) {
        int nl = w * 16 + rep;
        int node = base + nl;
        float4 a;
        if (node < N_NODES) {
            float d = g_dinv[node];
            float v = (lane < F_IN) ? sXA[nl * XA_STRIDE + lane] * d : 0.0f;
            a = bb;
            #pragma unroll
            for (int k = 0; k < F_IN; k++) {
                float xk = __shfl_sync(0xffffffffu, v, k);
                a.x += xk * w1r[k].x; a.y += xk * w1r[k].y;
                a.z += xk * w1r[k].z; a.w += xk * w1r[k].w;
            }
            a.x = fmaxf(a.x, 0.f); a.y = fmaxf(a.y, 0.f);
            a.z = fmaxf(a.z, 0.f); a.w = fmaxf(a.w, 0.f);
        } else {
            a = make_float4(0.f, 0.f, 0.f, 0.f);
        }
        *(float4*)(sH + nl * G2_HSTRIDE + lane * 4) = a;
    }
    __syncthreads();

    // stage 3 (phase B): thread = (node pair, 5-output group)
    int fg = tid & 3;          // outputs fg*5..fg*5+4
    int nl = tid >> 2;         // rows nl, nl+64
    float acc0[5] = {0,0,0,0,0}, acc1[5] = {0,0,0,0,0};
    #pragma unroll 4
    for (int k = 0; k < HID; k++) {
        float h0 = sH[nl * G2_HSTRIDE + k];
        float h1 = sH[(nl + 64) * G2_HSTRIDE + k];
        #pragma unroll
        for (int j = 0; j < 5; j++) {
            float wv = sWc[k * WCP + fg * 5 + j];
            acc0[j] += h0 * wv;
            acc1[j] += h1 * wv;
        }
    }
    int n0 = base + nl, n1 = base + nl + 64;
    if (n0 < N_NODES) {
        float d = g_dinv[n0];
        #pragma unroll
        for (int j = 0; j < 5; j++) g_z[(size_t)n0 * P2 + fg * 5 + j] = acc0[j] * d;
    }
    if (n1 < N_NODES) {
        float d = g_dinv[n1];
        #pragma unroll
        for (int j = 0; j < 5; j++) g_z[(size_t)n1 * P2 + fg * 5 + j] = acc1[j] * d;
    }
}

// ---------------- agg2 + fused mean-pool: warp per node, lanes 0..19 ----------------
__global__ void k_agg2(const int* __restrict__ batch) {
    int warp = (blockIdx.x * blockDim.x + threadIdx.x) >> 5;
    int lane = threadIdx.x & 31;
    if (warp >= N_NODES) return;
    int node = warp;
    bool act = lane < WCP;
    float acc = act ? g_z[(size_t)node * P2 + lane] : 0.0f;  // self loop

    int beg = g_rowptr[node], end = g_rowptr[node + 1];
    for (int j = beg; j < end; j += 32) {
        int n = min(32, end - j);
        int s = (lane < n) ? __ldg(&g_csr[j + lane]) : 0;
        int t = 0;
        for (; t + 4 <= n; t += 4) {
            int s0 = __shfl_sync(0xffffffffu, s, t + 0);
            int s1 = __shfl_sync(0xffffffffu, s, t + 1);
            int s2 = __shfl_sync(0xffffffffu, s, t + 2);
            int s3 = __shfl_sync(0xffffffffu, s, t + 3);
            if (act) {
                acc += g_z[(size_t)s0 * P2 + lane] + g_z[(size_t)s1 * P2 + lane]
                     + g_z[(size_t)s2 * P2 + lane] + g_z[(size_t)s3 * P2 + lane];
            }
        }
        for (; t < n; t++) {
            int sv = __shfl_sync(0xffffffffu, s, t);
            if (act) acc += g_z[(size_t)sv * P2 + lane];
        }
    }
    float d = g_dinv[node];
    int g = __ldg(&batch[node]);
    if (lane < F_OUT) atomicAdd(&g_pool[g * F_OUT + lane], acc * d);
    if (lane == 0) atomicAdd(&g_cnt[g], 1);
}

// ---------------- final: out = pool/cnt + bc ----------------
__global__ void k_final(float* __restrict__ out) {
    int idx = blockIdx.x * blockDim.x + threadIdx.x;
    if (idx >= NUM_GRAPHS * F_OUT) return;
    int g = idx / F_OUT, f = idx - g * F_OUT;
    float inv = 1.0f / fmaxf((float)g_cnt[g], 1.0f);
    out[idx] = g_pool[idx] * inv + g_bc[f];
}

// ---------------- launch ----------------
extern "C" void kernel_launch(void* const* d_in, const int* in_sizes, int n_in,
                              void* d_out, int out_size) {
    const float* x    = (const float*)d_in[0];
    const int*   esrc = (const int*)d_in[1];
    const int*   edst = (const int*)d_in[2];
    const int*   batch= (const int*)d_in[3];
    const float* W1   = (const float*)d_in[4];
    const float* b1   = (const float*)d_in[5];
    const float* W2   = (const float*)d_in[6];
    const float* b2   = (const float*)d_in[7];
    const float* Wlin = (const float*)d_in[8];
    const float* blin = (const float*)d_in[9];
    float* out = (float*)d_out;

    const int smem2 = (G2_TILE * G2_HSTRIDE + HID * WCP + G2_TILE * XA_STRIDE)
                      * (int)sizeof(float);   // ~86.5 KB
    static int attr_set = 0;
    if (!attr_set) {
        cudaFuncSetAttribute(k_agg1gemm, cudaFuncAttributeMaxDynamicSharedMemorySize, smem2);
        attr_set = 1;
    }

    k_hist    <<<NB_HIST + NB_TAIL, 256>>>(edst, W2, Wlin, b2, blin);
    k_scan1   <<<SCAN_NB, SCAN_B>>>();
    k_scan23  <<<(N_NODES + 255) / 256, 256>>>(x);
    k_fill    <<<NB_HIST, 256>>>(esrc, edst);
    k_agg1gemm<<<(N_NODES + G2_TILE - 1) / G2_TILE, 256, smem2>>>(W1, b1);
    k_agg2    <<<(N_NODES * 32 + 255) / 256, 256>>>(batch);
    k_final   <<<(NUM_GRAPHS * F_OUT + 255) / 256, 256>>>(out);
}

// round 10
// speedup vs baseline: 1.1749x; 1.1749x over previous
#include <cuda_runtime.h>
#include <math.h>

#define N_NODES    100000
#define N_EDGES    1600000
#define NUM_GRAPHS 4096
#define HID        128
#define F_IN       11
#define F_OUT      19
#define P1         16      // padded input row (floats)
#define P2         24      // padded z row (floats)
#define WCP        20      // padded Wc columns (col 19 = zero)
#define SCAN_B     512
#define SCAN_NB    ((N_NODES + SCAN_B - 1) / SCAN_B)
#define NB_HIST    ((N_EDGES + 255) / 256)
// tail work in k_hist: pool zero | cnt zero | Wc | bc
#define TAIL_POOL  (NUM_GRAPHS * F_OUT)
#define TAIL_CNT   (TAIL_POOL + NUM_GRAPHS)
#define TAIL_WC    (TAIL_CNT + HID * WCP)
#define TAIL_BC    (TAIL_WC + F_OUT)
#define NB_TAIL    ((TAIL_BC + 255) / 256)

#define G2_TILE    128
#define G2_HSTRIDE 132

// ---------------- static device scratch (zero-initialized at load) ----------------
__device__ float g_xs [(size_t)N_NODES * P1];   // dinv-scaled padded input
__device__ float g_xa [(size_t)N_NODES * P1];   // aggregated input
__device__ float g_z  [(size_t)N_NODES * P2];   // dinv * (h1 @ Wc)
__device__ float g_Wc [HID * WCP];              // W2 @ Wlin (padded)
__device__ float g_bc [F_OUT];                  // b2 @ Wlin + blin
__device__ float g_dinv[N_NODES];
__device__ int   g_ecnt[N_NODES];               // self-cleaned by k_scan23
__device__ int   g_rank[N_EDGES];               // rank of edge within its dst bucket
__device__ int   g_rowptr[N_NODES + 1];
__device__ int   g_csr[N_EDGES];
__device__ int   g_blksum[SCAN_NB];
__device__ float g_pool[NUM_GRAPHS * F_OUT];    // zeroed in k_hist tail
__device__ int   g_cnt[NUM_GRAPHS];             // zeroed in k_hist tail

// ---------------- hist over dst (stores rank) + tail: zero pool/cnt, Wc, bc ----------------
__global__ void k_hist(const int* __restrict__ dst,
                       const float* __restrict__ W2, const float* __restrict__ Wlin,
                       const float* __restrict__ b2, const float* __restrict__ blin) {
    int b = blockIdx.x;
    if (b < NB_HIST) {
        int e = b * 256 + threadIdx.x;
        if (e < N_EDGES) {
            int d = __ldg(&dst[e]);
            g_rank[e] = atomicAdd(&g_ecnt[d], 1);
        }
        return;
    }
    int j = (b - NB_HIST) * 256 + threadIdx.x;
    if (j < TAIL_POOL) { g_pool[j] = 0.0f; return; }
    if (j < TAIL_CNT)  { g_cnt[j - TAIL_POOL] = 0; return; }
    if (j < TAIL_WC) {
        int i = j - TAIL_CNT;
        int k = i / WCP, f = i % WCP;
        float acc = 0.0f;
        if (f < F_OUT) {
            #pragma unroll 8
            for (int m = 0; m < HID; m++)
                acc += __ldg(&W2[k * HID + m]) * __ldg(&Wlin[m * F_OUT + f]);
        }
        g_Wc[i] = acc;
        return;
    }
    if (j < TAIL_BC) {
        int f = j - TAIL_WC;
        float acc = __ldg(&blin[f]);
        #pragma unroll 8
        for (int m = 0; m < HID; m++)
            acc += __ldg(&b2[m]) * __ldg(&Wlin[m * F_OUT + f]);
        g_bc[f] = acc;
    }
}

// ---------------- scan phase 1: per-block exclusive scan of g_ecnt ----------------
__global__ void k_scan1() {
    __shared__ int warp_sums[16];
    int i = blockIdx.x * SCAN_B + threadIdx.x;
    int v = (i < N_NODES) ? g_ecnt[i] : 0;
    int lane = threadIdx.x & 31, wid = threadIdx.x >> 5;
    int incl = v;
    #pragma unroll
    for (int d = 1; d < 32; d <<= 1) {
        int t = __shfl_up_sync(0xffffffffu, incl, d);
        if (lane >= d) incl += t;
    }
    if (lane == 31) warp_sums[wid] = incl;
    __syncthreads();
    if (wid == 0) {
        int s = (lane < 16) ? warp_sums[lane] : 0;
        #pragma unroll
        for (int d = 1; d < 16; d <<= 1) {
            int t = __shfl_up_sync(0xffffffffu, s, d);
            if (lane >= d) s += t;
        }
        if (lane < 16) warp_sums[lane] = s;
    }
    __syncthreads();
    int offset = (wid > 0) ? warp_sums[wid - 1] : 0;
    if (i < N_NODES) g_rowptr[i] = offset + incl - v;
    if (threadIdx.x == SCAN_B - 1) g_blksum[blockIdx.x] = offset + incl;
}

// ---------------- scan 2+3 fused: every block scans blksum in smem, then finalizes ----------------
// also: dinv, xs = dinv*x (padded), ecnt self-clean, rowptr tail
__global__ void k_scan23(const float* __restrict__ x) {
    __shared__ int pref[SCAN_NB];
    __shared__ int ws[8];
    int tid = threadIdx.x;                      // 256
    {
        int lane = tid & 31, w = tid >> 5;
        int v = (tid < SCAN_NB) ? g_blksum[tid] : 0;
        int incl = v;
        #pragma unroll
        for (int d = 1; d < 32; d <<= 1) {
            int u = __shfl_up_sync(0xffffffffu, incl, d);
            if (lane >= d) incl += u;
        }
        if (lane == 31) ws[w] = incl;
        __syncthreads();
        if (w == 0) {
            int s = (lane < 8) ? ws[lane] : 0;
            #pragma unroll
            for (int d = 1; d < 8; d <<= 1) {
                int u = __shfl_up_sync(0xffffffffu, s, d);
                if (lane >= d) s += u;
            }
            if (lane < 8) ws[lane] = s;
        }
        __syncthreads();
        int off = (w > 0) ? ws[w - 1] : 0;
        if (tid < SCAN_NB) pref[tid] = off + incl - v;
        __syncthreads();
    }
    int i = blockIdx.x * 256 + tid;
    if (i >= N_NODES) return;
    if (i == 0) g_rowptr[N_NODES] = N_EDGES;
    int r = g_rowptr[i] + pref[i / SCAN_B];
    g_rowptr[i] = r;
    int e = g_ecnt[i];
    g_ecnt[i] = 0;                               // self-clean for next replay
    float d = rsqrtf((float)(e + 1));
    g_dinv[i] = d;
    float row[P1];
    #pragma unroll
    for (int f = 0; f < F_IN; f++) row[f] = __ldg(&x[i * F_IN + f]) * d;
    #pragma unroll
    for (int f = F_IN; f < P1; f++) row[f] = 0.0f;
    float4* dst = (float4*)(g_xs + (size_t)i * P1);
    dst[0] = make_float4(row[0], row[1], row[2], row[3]);
    dst[1] = make_float4(row[4], row[5], row[6], row[7]);
    dst[2] = make_float4(row[8], row[9], row[10], row[11]);
    dst[3] = make_float4(row[12], row[13], row[14], row[15]);
}

// ---------------- CSR fill: atomic-free (rank precomputed in hist) ----------------
__global__ void k_fill(const int* __restrict__ src, const int* __restrict__ dst) {
    int e = blockIdx.x * blockDim.x + threadIdx.x;
    if (e < N_EDGES) {
        int d = __ldg(&dst[e]);
        int p = __ldg(&g_rowptr[d]) + g_rank[e];
        g_csr[p] = __ldg(&src[e]);
    }
}

// ---------------- agg1: half-warp per node over 16 padded features (high occupancy) ----------------
__global__ void k_agg1() {
    int half = (blockIdx.x * blockDim.x + threadIdx.x) >> 4;
    int lane = threadIdx.x & 15;
    if (half >= N_NODES) return;
    int node = half;
    float acc = g_xs[(size_t)node * P1 + lane];   // self loop
    int j = g_rowptr[node], end = g_rowptr[node + 1];
    for (; j + 4 <= end; j += 4) {
        int s0 = __ldg(&g_csr[j]);
        int s1 = __ldg(&g_csr[j + 1]);
        int s2 = __ldg(&g_csr[j + 2]);
        int s3 = __ldg(&g_csr[j + 3]);
        acc += g_xs[(size_t)s0 * P1 + lane] + g_xs[(size_t)s1 * P1 + lane]
             + g_xs[(size_t)s2 * P1 + lane] + g_xs[(size_t)s3 * P1 + lane];
    }
    for (; j < end; j++)
        acc += g_xs[(size_t)__ldg(&g_csr[j]) * P1 + lane];
    g_xa[(size_t)node * P1 + lane] = acc;
}

// ---------------- fused GEMM1+GEMM2': tile of 128 nodes ----------------
// phase A: h1 = relu(dinv*xa @ W1 + b1) into smem tile (stride 132)
// phase B: z = dinv * (h1 @ Wc) to global
__global__ void k_gemm12(const float* __restrict__ W1, const float* __restrict__ b1) {
    extern __shared__ float sh[];
    float* sH  = sh;                          // [128][132]
    float* sWc = sh + G2_TILE * G2_HSTRIDE;   // [128][20]
    int tid = threadIdx.x;                    // 256
    int lane = tid & 31, w = tid >> 5;        // 8 warps
    int base = blockIdx.x * G2_TILE;

    for (int i = tid; i < HID * WCP; i += 256) sWc[i] = g_Wc[i];

    // preload W1 column-slice + bias into registers
    float4 w1r[F_IN];
    #pragma unroll
    for (int k = 0; k < F_IN; k++)
        w1r[k] = __ldg(((const float4*)(W1 + k * HID)) + lane);
    float4 bb = __ldg(((const float4*)b1) + lane);

    // phase A: warp w computes nodes [w*16, w*16+16)
    #pragma unroll 2
    for (int rep = 0; rep < 16; rep++) {
        int nl = w * 16 + rep;
        int node = base + nl;
        float4 a;
        if (node < N_NODES) {
            float d = g_dinv[node];
            float v = (lane < F_IN) ? g_xa[(size_t)node * P1 + lane] * d : 0.0f;
            a = bb;
            #pragma unroll
            for (int k = 0; k < F_IN; k++) {
                float xk = __shfl_sync(0xffffffffu, v, k);
                a.x += xk * w1r[k].x; a.y += xk * w1r[k].y;
                a.z += xk * w1r[k].z; a.w += xk * w1r[k].w;
            }
            a.x = fmaxf(a.x, 0.f); a.y = fmaxf(a.y, 0.f);
            a.z = fmaxf(a.z, 0.f); a.w = fmaxf(a.w, 0.f);
        } else {
            a = make_float4(0.f, 0.f, 0.f, 0.f);
        }
        *(float4*)(sH + nl * G2_HSTRIDE + lane * 4) = a;
    }
    __syncthreads();

    // phase B: thread = (node pair, 5-output group)
    int fg = tid & 3;          // outputs fg*5..fg*5+4
    int nl = tid >> 2;         // rows nl, nl+64
    float acc0[5] = {0,0,0,0,0}, acc1[5] = {0,0,0,0,0};
    #pragma unroll 4
    for (int k = 0; k < HID; k++) {
        float h0 = sH[nl * G2_HSTRIDE + k];
        float h1 = sH[(nl + 64) * G2_HSTRIDE + k];
        #pragma unroll
        for (int j = 0; j < 5; j++) {
            float wv = sWc[k * WCP + fg * 5 + j];
            acc0[j] += h0 * wv;
            acc1[j] += h1 * wv;
        }
    }
    int n0 = base + nl, n1 = base + nl + 64;
    if (n0 < N_NODES) {
        float d = g_dinv[n0];
        #pragma unroll
        for (int j = 0; j < 5; j++) g_z[(size_t)n0 * P2 + fg * 5 + j] = acc0[j] * d;
    }
    if (n1 < N_NODES) {
        float d = g_dinv[n1];
        #pragma unroll
        for (int j = 0; j < 5; j++) g_z[(size_t)n1 * P2 + fg * 5 + j] = acc1[j] * d;
    }
}

// ---------------- agg2 + fused mean-pool: warp per node, lanes 0..19 ----------------
__global__ void k_agg2(const int* __restrict__ batch) {
    int warp = (blockIdx.x * blockDim.x + threadIdx.x) >> 5;
    int lane = threadIdx.x & 31;
    if (warp >= N_NODES) return;
    int node = warp;
    bool act = lane < WCP;
    float acc = act ? g_z[(size_t)node * P2 + lane] : 0.0f;  // self loop

    int beg = g_rowptr[node], end = g_rowptr[node + 1];
    for (int j = beg; j < end; j += 32) {
        int n = min(32, end - j);
        int s = (lane < n) ? __ldg(&g_csr[j + lane]) : 0;
        int t = 0;
        for (; t + 4 <= n; t += 4) {
            int s0 = __shfl_sync(0xffffffffu, s, t + 0);
            int s1 = __shfl_sync(0xffffffffu, s, t + 1);
            int s2 = __shfl_sync(0xffffffffu, s, t + 2);
            int s3 = __shfl_sync(0xffffffffu, s, t + 3);
            if (act) {
                acc += g_z[(size_t)s0 * P2 + lane] + g_z[(size_t)s1 * P2 + lane]
                     + g_z[(size_t)s2 * P2 + lane] + g_z[(size_t)s3 * P2 + lane];
            }
        }
        for (; t < n; t++) {
            int sv = __shfl_sync(0xffffffffu, s, t);
            if (act) acc += g_z[(size_t)sv * P2 + lane];
        }
    }
    float d = g_dinv[node];
    int g = __ldg(&batch[node]);
    if (lane < F_OUT) atomicAdd(&g_pool[g * F_OUT + lane], acc * d);
    if (lane == 0) atomicAdd(&g_cnt[g], 1);
}

// ---------------- final: out = pool/cnt + bc ----------------
__global__ void k_final(float* __restrict__ out) {
    int idx = blockIdx.x * blockDim.x + threadIdx.x;
    if (idx >= NUM_GRAPHS * F_OUT) return;
    int g = idx / F_OUT, f = idx - g * F_OUT;
    float inv = 1.0f / fmaxf((float)g_cnt[g], 1.0f);
    out[idx] = g_pool[idx] * inv + g_bc[f];
}

// ---------------- launch ----------------
extern "C" void kernel_launch(void* const* d_in, const int* in_sizes, int n_in,
                              void* d_out, int out_size) {
    const float* x    = (const float*)d_in[0];
    const int*   esrc = (const int*)d_in[1];
    const int*   edst = (const int*)d_in[2];
    const int*   batch= (const int*)d_in[3];
    const float* W1   = (const float*)d_in[4];
    const float* b1   = (const float*)d_in[5];
    const float* W2   = (const float*)d_in[6];
    const float* b2   = (const float*)d_in[7];
    const float* Wlin = (const float*)d_in[8];
    const float* blin = (const float*)d_in[9];
    float* out = (float*)d_out;

    const int smem2 = (G2_TILE * G2_HSTRIDE + HID * WCP) * (int)sizeof(float);  // 77.8 KB
    static int attr_set = 0;
    if (!attr_set) {
        cudaFuncSetAttribute(k_gemm12, cudaFuncAttributeMaxDynamicSharedMemorySize, smem2);
        attr_set = 1;
    }

    k_hist  <<<NB_HIST + NB_TAIL, 256>>>(edst, W2, Wlin, b2, blin);
    k_scan1 <<<SCAN_NB, SCAN_B>>>();
    k_scan23<<<(N_NODES + 255) / 256, 256>>>(x);
    k_fill  <<<NB_HIST, 256>>>(esrc, edst);
    k_agg1  <<<(N_NODES * 16 + 255) / 256, 256>>>();
    k_gemm12<<<(N_NODES + G2_TILE - 1) / G2_TILE, 256, smem2>>>(W1, b1);
    k_agg2  <<<(N_NODES * 32 + 255) / 256, 256>>>(batch);
    k_final <<<(NUM_GRAPHS * F_OUT + 255) / 256, 256>>>(out);
}